// round 10
// baseline (speedup 1.0000x reference)
#include <cuda_runtime.h>
#include <cuda_fp16.h>

#define NBLK 128
#define NTHR 256
#define T_STEPS 512
#define PLEN 64

#define RING 4
#define LA 3
#define S0 9                    // layer0: 8 H-stages + 1 X-stage (K=1152)
#define S12 16                  // layers 1/2: 8 H + 8 X (K=2048)
#define SR 24                   // smem row stride (halves) = 48B, conflict-free
#define AWB 3072                // A bytes per warp-stage: 64 rows x 48B
#define STGB 4608               // warp-stage bytes (A 3072 + B 1536)
#define WREG (RING * STGB)
#define GOFF (8 * WREG)         // gates: 8 bufs x 64x33 f32 = 67584B (fc scratch aliases)
#define SMEM_BYTES (GOFF + 67584)

#define L0SZ (128 * S0 * 4096)
#define L12SZ (128 * S12 * 4096)

// ---------------- device state ----------------
__device__ __half g_Wp0[L0SZ];
__device__ __half g_Wp1[L12SZ];
__device__ __half g_Wp2[L12SZ];
__device__ __half g_Wfch[128 * 1024];
__device__ float  g_bsum[3 * 4096];
__device__ __half g_In0[64 * 128];
__device__ __half g_X1[64 * 1024];
__device__ __half g_X2[64 * 1024];
__device__ __half g_Xfc[64 * 1024];
__device__ __half g_Hst[3][2][64 * 1024];
__device__ float  g_Cst[3 * 64 * 1024];
__device__ unsigned g_count;
__device__ unsigned g_gen;

// ---------------- helpers ----------------
__device__ __forceinline__ float sigf(float v) { return 1.0f / (1.0f + expf(-v)); }
__device__ __forceinline__ unsigned smaddr(const void* p) {
    return (unsigned)__cvta_generic_to_shared(p);
}
__device__ __forceinline__ void cp16(unsigned dst, const void* src) {
    asm volatile("cp.async.cg.shared.global [%0], [%1], 16;" :: "r"(dst), "l"(src));
}
__device__ __forceinline__ void cp_commit() { asm volatile("cp.async.commit_group;"); }

__device__ __forceinline__ void ldsm4(unsigned& r0, unsigned& r1, unsigned& r2, unsigned& r3,
                                      unsigned addr) {
    asm volatile("ldmatrix.sync.aligned.m8n8.x4.shared.b16 {%0,%1,%2,%3}, [%4];"
                 : "=r"(r0), "=r"(r1), "=r"(r2), "=r"(r3) : "r"(addr));
}
__device__ __forceinline__ void mma16816(float c[4],
    unsigned a0, unsigned a1, unsigned a2, unsigned a3, unsigned b0, unsigned b1) {
    asm volatile("mma.sync.aligned.m16n8k16.row.col.f32.f16.f16.f32 "
        "{%0,%1,%2,%3}, {%4,%5,%6,%7}, {%8,%9}, {%0,%1,%2,%3};"
        : "+f"(c[0]), "+f"(c[1]), "+f"(c[2]), "+f"(c[3])
        : "r"(a0), "r"(a1), "r"(a2), "r"(a3), "r"(b0), "r"(b1));
}

__device__ __forceinline__ void grid_sync() {
    __syncthreads();
    if (threadIdx.x == 0) {
        unsigned gen;
        asm volatile("ld.volatile.global.u32 %0, [%1];" : "=r"(gen) : "l"(&g_gen));
        unsigned arr;
        asm volatile("atom.release.gpu.global.add.u32 %0, [%1], %2;"
                     : "=r"(arr) : "l"(&g_count), "r"(1u));
        if (arr == NBLK - 1) {
            *(volatile unsigned*)&g_count = 0;
            asm volatile("red.release.gpu.global.add.u32 [%0], %1;" :: "l"(&g_gen), "r"(1u));
        } else {
            unsigned cur;
            do {
                asm volatile("ld.acquire.gpu.global.u32 %0, [%1];" : "=r"(cur) : "l"(&g_gen));
            } while (cur == gen);
        }
    }
    __syncthreads();
}

// ---------------- packing / init (same layout as R4) ----------------
// Wp[((bc*S + s)*32 + col)*128 + kk]; col = gate*8 + nl; H-part first
// (s<8 -> Whh k=s*128+kk; s>=8 -> Wih); row = gate*1024 + bc*8 + nl.
__global__ void pack_all(const float* __restrict__ Wih0, const float* __restrict__ Whh0,
                         const float* __restrict__ Wih1, const float* __restrict__ Whh1,
                         const float* __restrict__ Wih2, const float* __restrict__ Whh2) {
    int idx = blockIdx.x * blockDim.x + threadIdx.x;
    const float *Wih, *Whh;
    __half* Wp;
    int S, Kin, i = idx;
    if (i < L0SZ)               { Wp = g_Wp0; S = S0;  Kin = 128;  Wih = Wih0; Whh = Whh0; }
    else if (i < L0SZ + L12SZ)  { i -= L0SZ;  Wp = g_Wp1; S = S12; Kin = 1024; Wih = Wih1; Whh = Whh1; }
    else if (i < L0SZ + 2*L12SZ){ i -= L0SZ + L12SZ; Wp = g_Wp2; S = S12; Kin = 1024; Wih = Wih2; Whh = Whh2; }
    else return;
    int kk   = i & 127;
    int col  = (i >> 7) & 31;
    int rest = i >> 12;
    int s    = rest % S;
    int bc   = rest / S;
    int row  = ((col >> 3) << 10) + bc * 8 + (col & 7);
    float v  = (s < 8) ? Whh[row * 1024 + s * 128 + kk]
                       : Wih[row * Kin + (s - 8) * 128 + kk];
    Wp[i] = __float2half(v);
}

__global__ void pack_fc(const float* __restrict__ Wfc) {
    int i = blockIdx.x * blockDim.x + threadIdx.x;
    if (i < 128 * 1024) g_Wfch[i] = __float2half(Wfc[i]);
}

__global__ void init_state(const float* __restrict__ x, const float* __restrict__ h0,
                           const float* __restrict__ c0,
                           const float* __restrict__ bih0, const float* __restrict__ bhh0,
                           const float* __restrict__ bih1, const float* __restrict__ bhh1,
                           const float* __restrict__ bih2, const float* __restrict__ bhh2,
                           float* __restrict__ out) {
    int i = blockIdx.x * blockDim.x + threadIdx.x;
    if (i < 8192) { float v = x[i]; g_In0[i] = __float2half(v); out[i] = v; }
    if (i < 3 * 65536) {
        g_Hst[i >> 16][0][i & 65535] = __float2half(h0[i]);
        g_Cst[i] = c0[i];
    }
    if (i < 4096) {
        g_bsum[i]        = bih0[i] + bhh0[i];
        g_bsum[4096 + i] = bih1[i] + bhh1[i];
        g_bsum[8192 + i] = bih2[i] + bhh2[i];
    }
}

// ---------------- main persistent kernel ----------------
extern __shared__ char smch[];

struct Ctx {
    int tid, lane, w, bc;
    unsigned smb, wbase;      // warp-private ring base
    unsigned aL, bL;          // ldmatrix lane offsets (bytes within warp-stage)
    int cr, cc, kcol;         // copy indices: row base, 16B-chunk sel, k column (halves)
};

// warp-private stage load: A = acts rows 0..63 (this warp's 16 k), B = 32 gate cols
__device__ __forceinline__ void load_stage(const Ctx& cx,
    const __half* __restrict__ Hp, const __half* __restrict__ Xin, int ldX,
    const __half* __restrict__ Wblk, int s, int slot)
{
    unsigned sb = cx.wbase + (unsigned)slot * STGB;
    const __half* asrc; int ld;
    if (s < 8) { asrc = Hp + s * 128; ld = 1024; }
    else       { asrc = Xin + (s - 8) * 128; ld = ldX; }
    asrc += cx.kcol;
#pragma unroll
    for (int ph = 0; ph < 4; ++ph) {
        int r = cx.cr + ph * 16;
        cp16(sb + (unsigned)(r * 48 + cx.cc * 16), asrc + r * ld);
    }
    const __half* bsrc = Wblk + (size_t)s * 4096 + cx.kcol;
#pragma unroll
    for (int ph = 0; ph < 2; ++ph) {
        int col = cx.cr + ph * 16;
        cp16(sb + (unsigned)(AWB + col * 48 + cx.cc * 16), bsrc + col * 128);
    }
}

__device__ __forceinline__ void gemm_epi(const Ctx& cx, int S,
    const __half* __restrict__ Hp, const __half* __restrict__ Xin, int ldX,
    const __half* __restrict__ Wblk, bool esync,
    const float* __restrict__ bsumL, float* __restrict__ Cl,
    __half* __restrict__ Hn, __half* __restrict__ Xn)
{
    float acc[4][4][4];
#pragma unroll
    for (int a = 0; a < 4; ++a)
#pragma unroll
        for (int b = 0; b < 4; ++b)
#pragma unroll
            for (int q = 0; q < 4; ++q) acc[a][b][q] = 0.f;

    // prologue: LA H-stages (barrier-independent)
#pragma unroll
    for (int s = 0; s < LA; ++s) {
        load_stage(cx, Hp, Xin, ldX, Wblk, s, s);
        cp_commit();
    }

#pragma unroll 1
    for (int s = 0; s < S; ++s) {
        asm volatile("cp.async.wait_group %0;" :: "n"(LA - 1));
        int u = s + LA;
        if (esync && u == 8) grid_sync();       // publish X before first X-stage load
        if (u < S) load_stage(cx, Hp, Xin, ldX, Wblk, u, u & (RING - 1));
        cp_commit();

        unsigned sb = cx.wbase + (unsigned)(s & (RING - 1)) * STGB;
        unsigned p0[4], p1[4];
        ldsm4(p0[0], p0[1], p0[2], p0[3], sb + AWB + cx.bL);
        ldsm4(p1[0], p1[1], p1[2], p1[3], sb + AWB + cx.bL + 768u);
#pragma unroll
        for (int mt = 0; mt < 4; ++mt) {
            unsigned a0, a1, a2, a3;
            ldsm4(a0, a1, a2, a3, sb + cx.aL + mt * 768u);
            mma16816(acc[mt][0], a0, a1, a2, a3, p0[0], p0[1]);
            mma16816(acc[mt][1], a0, a1, a2, a3, p0[2], p0[3]);
            mma16816(acc[mt][2], a0, a1, a2, a3, p1[0], p1[1]);
            mma16816(acc[mt][3], a0, a1, a2, a3, p1[2], p1[3]);
        }
    }

    // store partial gates (warp-private buffer)
    {
        float* gk = (float*)(smch + GOFF) + cx.w * (64 * 33);
        int r = cx.lane >> 2, c2 = (cx.lane & 3) * 2;
#pragma unroll
        for (int mt = 0; mt < 4; ++mt)
#pragma unroll
            for (int nt = 0; nt < 4; ++nt) {
                int row = mt * 16 + r, col = nt * 8 + c2;
                gk[row * 33 + col]           = acc[mt][nt][0];
                gk[row * 33 + col + 1]       = acc[mt][nt][1];
                gk[(row + 8) * 33 + col]     = acc[mt][nt][2];
                gk[(row + 8) * 33 + col + 1] = acc[mt][nt][3];
            }
    }
    __syncthreads();

    // fused LSTM cell: 512 items (64 batch x 8 hidden), 2 per thread
    const float* gates = (const float*)(smch + GOFF);
#pragma unroll
    for (int k = 0; k < 2; ++k) {
        int item = cx.tid + k * 256;
        int b = item >> 3, nl = item & 7;
        int ng = cx.bc * 8 + nl;
        int e = b * 33 + nl;
        float gi = 0.f, gf = 0.f, gg = 0.f, go = 0.f;
#pragma unroll
        for (int kb = 0; kb < 8; ++kb) {
            const float* g = gates + kb * (64 * 33);
            gi += g[e];
            gf += g[e + 8];
            gg += g[e + 16];
            go += g[e + 24];
        }
        gi += bsumL[ng]; gf += bsumL[1024 + ng];
        gg += bsumL[2048 + ng]; go += bsumL[3072 + ng];
        float c  = Cl[b * 1024 + ng];
        float cn = sigf(gf) * c + sigf(gi) * tanhf(gg);
        float h  = sigf(go) * tanhf(cn);
        Cl[b * 1024 + ng] = cn;
        __half hh = __float2half(h);
        Hn[b * 1024 + ng] = hh;
        Xn[b * 1024 + ng] = hh;
    }
    __syncthreads();
}

__global__ void __launch_bounds__(NTHR, 1)
lstm_main(const float* __restrict__ x, const float* __restrict__ bfc,
          float* __restrict__ out)
{
    Ctx cx;
    cx.tid = threadIdx.x; cx.bc = blockIdx.x;
    cx.lane = cx.tid & 31; cx.w = cx.tid >> 5;
    cx.smb = smaddr(smch);
    cx.wbase = cx.smb + (unsigned)cx.w * WREG;
    cx.cr = cx.lane >> 1;
    cx.cc = cx.lane & 1;
    cx.kcol = cx.w * 16 + cx.cc * 8;
    cx.aL = (unsigned)(((((cx.lane >> 3) & 1) * 8 + (cx.lane & 7)) * SR
                        + (cx.lane >> 4) * 8) * 2);
    cx.bL = (unsigned)(((((cx.lane >> 4) & 1) * 8 + (cx.lane & 7)) * SR
                        + ((cx.lane >> 3) & 1) * 8) * 2);
    const int tid = cx.tid, bc = cx.bc;

    const __half* Wb0 = g_Wp0 + (size_t)bc * S0 * 4096;
    const __half* Wb1 = g_Wp1 + (size_t)bc * S12 * 4096;
    const __half* Wb2 = g_Wp2 + (size_t)bc * S12 * 4096;
    const int br = bc >> 4, cg = bc & 15;

#pragma unroll 1
    for (int t = 0; t < T_STEPS - 1; ++t) {
        int p = t & 1;

        // L0 (embedded barrier publishes In0 from previous fc)
        gemm_epi(cx, S0, g_Hst[0][p], g_In0, 128, Wb0, true,
                 g_bsum, g_Cst, g_Hst[0][p ^ 1], g_X1);
        // L1 (embedded barrier publishes X1 + h0)
        gemm_epi(cx, S12, g_Hst[1][p], g_X1, 1024, Wb1, true,
                 g_bsum + 4096, g_Cst + 65536, g_Hst[1][p ^ 1], g_X2);
        // L2 (embedded barrier publishes X2 + h1)
        gemm_epi(cx, S12, g_Hst[2][p], g_X2, 1024, Wb2, true,
                 g_bsum + 8192, g_Cst + 131072, g_Hst[2][p ^ 1], g_Xfc);
        grid_sync();   // publish Xfc + h2

        // ---- fc: stage h-slice (8x1024) + W-slice (8 rows, stride 1032) into smem
        {
            unsigned hs = cx.smb + GOFF;
            unsigned ws = hs + 16384;
            const __half* hsrc = g_Xfc + br * 8 * 1024;
            const __half* wsrc = g_Wfch + cg * 8 * 1024;
#pragma unroll
            for (int i = 0; i < 4; ++i) {
                int q = tid + i * 256;
                cp16(hs + (unsigned)q * 16u, hsrc + q * 8);
                int rw = q >> 7, cw = q & 127;
                cp16(ws + (unsigned)(rw * 2064 + cw * 16), wsrc + rw * 1024 + cw * 8);
            }
            cp_commit();
            asm volatile("cp.async.wait_group 0;");
            __syncthreads();

            int o = tid >> 2, part = tid & 3;
            int bl = o >> 3, dl = o & 7;
            const float4* hp = (const float4*)(smch + GOFF + bl * 2048) + part * 32;
            const float4* wp = (const float4*)(smch + GOFF + 16384 + dl * 2064) + part * 32;
            float acc = 0.f;
#pragma unroll
            for (int k = 0; k < 32; ++k) {
                float4 hv = hp[k];
                float4 wv = wp[k];
                const __half2* h2 = (const __half2*)&hv;
                const __half2* w2 = (const __half2*)&wv;
#pragma unroll
                for (int j = 0; j < 4; ++j) {
                    float2 hf = __half22float2(h2[j]);
                    float2 wf = __half22float2(w2[j]);
                    acc = fmaf(hf.x, wf.x, acc);
                    acc = fmaf(hf.y, wf.y, acc);
                }
            }
            acc += __shfl_xor_sync(0xffffffff, acc, 1);
            acc += __shfl_xor_sync(0xffffffff, acc, 2);
            if (part == 0) {
                int b = br * 8 + bl;
                int d = cg * 8 + dl;
                float z = sigf(acc + bfc[d]);
                float v = (t + 1 < PLEN) ? x[(size_t)(t + 1) * 8192 + b * 128 + d] : z;
                out[(size_t)(t + 1) * 8192 + b * 128 + d] = v;
                g_In0[b * 128 + d] = __float2half(v);
            }
            __syncthreads();
        }
        // no trailing barrier: next step's L0 embeds the In0-publish barrier
    }
}

// ---------------- launch (lstm_main is launch #4 for ncu) ----------------
extern "C" void kernel_launch(void* const* d_in, const int* in_sizes, int n_in,
                              void* d_out, int out_size) {
    const float* x    = (const float*)d_in[0];
    const float* h0   = (const float*)d_in[1];
    const float* c0   = (const float*)d_in[2];
    const float* Wih0 = (const float*)d_in[3];
    const float* Whh0 = (const float*)d_in[4];
    const float* bih0 = (const float*)d_in[5];
    const float* bhh0 = (const float*)d_in[6];
    const float* Wih1 = (const float*)d_in[7];
    const float* Whh1 = (const float*)d_in[8];
    const float* bih1 = (const float*)d_in[9];
    const float* bhh1 = (const float*)d_in[10];
    const float* Wih2 = (const float*)d_in[11];
    const float* Whh2 = (const float*)d_in[12];
    const float* bih2 = (const float*)d_in[13];
    const float* bhh2 = (const float*)d_in[14];
    const float* Wfc  = (const float*)d_in[15];
    const float* bfc  = (const float*)d_in[16];
    float* out = (float*)d_out;

    static bool attr_done = false;
    if (!attr_done) {
        cudaFuncSetAttribute(lstm_main, cudaFuncAttributeMaxDynamicSharedMemorySize,
                             SMEM_BYTES);
        attr_done = true;
    }

    int total = L0SZ + 2 * L12SZ;
    pack_all<<<(total + 255) / 256, 256>>>(Wih0, Whh0, Wih1, Whh1, Wih2, Whh2);
    pack_fc<<<512, 256>>>(Wfc);
    init_state<<<768, 256>>>(x, h0, c0, bih0, bhh0, bih1, bhh1, bih2, bhh2, out);
    lstm_main<<<NBLK, NTHR, SMEM_BYTES>>>(x, bfc, out);
}

// round 11
// speedup vs baseline: 1.2162x; 1.2162x over previous
#include <cuda_runtime.h>
#include <cuda_fp16.h>

#define NBLK 128
#define NTHR 512
#define T_STEPS 512
#define PLEN 64

#define BK 128                // k-halves per stage
#define RING 4
#define LA 3
#define SA 136                // smem row stride in halves (BK + 8)
#define ASTAGE (64 * SA)      // halves
#define BSTAGE (32 * SA)      // halves
#define NKS 8                 // k-split warps
#define GATES_OFF (RING * (ASTAGE + BSTAGE))            // halves
#define WFC_OFF   (GATES_OFF + NKS * 64 * 33 * 2)       // gates: 8 bufs of 64x33 floats
#define SMEM_BYTES ((WFC_OFF + 8 * 1024) * 2)

#define S0 9                  // layer0: 8 H-stages + 1 X-stage (K=1152)
#define S12 16                // layers 1/2: 8 H + 8 X (K=2048)
#define L0SZ (128 * S0 * 4096)
#define L12SZ (128 * S12 * 4096)

// ---------------- device state ----------------
__device__ __half g_Wp0[L0SZ];
__device__ __half g_Wp1[L12SZ];
__device__ __half g_Wp2[L12SZ];
__device__ __half g_Wfch[128 * 1024];
__device__ float  g_bsum[3 * 4096];
__device__ __half g_In0[64 * 128];
__device__ __half g_X1[64 * 1024];
__device__ __half g_X2[64 * 1024];
__device__ __half g_Xfc[64 * 1024];
__device__ __half g_Hst[3][2][64 * 1024];
__device__ float  g_Cst[3 * 64 * 1024];
__device__ unsigned g_count;
__device__ unsigned g_gen;

// ---------------- helpers ----------------
__device__ __forceinline__ float sigf(float v) { return 1.0f / (1.0f + expf(-v)); }

__device__ __forceinline__ unsigned smaddr(const void* p) {
    return (unsigned)__cvta_generic_to_shared(p);
}
__device__ __forceinline__ void cp16(unsigned dst, const void* src) {
    asm volatile("cp.async.cg.shared.global [%0], [%1], 16;" :: "r"(dst), "l"(src));
}
__device__ __forceinline__ void cp_commit() { asm volatile("cp.async.commit_group;"); }

__device__ __forceinline__ void ldsm4(unsigned& r0, unsigned& r1, unsigned& r2, unsigned& r3,
                                      unsigned addr) {
    asm volatile("ldmatrix.sync.aligned.m8n8.x4.shared.b16 {%0,%1,%2,%3}, [%4];"
                 : "=r"(r0), "=r"(r1), "=r"(r2), "=r"(r3) : "r"(addr));
}
__device__ __forceinline__ void mma16816(float c[4],
    unsigned a0, unsigned a1, unsigned a2, unsigned a3, unsigned b0, unsigned b1) {
    asm volatile("mma.sync.aligned.m16n8k16.row.col.f32.f16.f16.f32 "
        "{%0,%1,%2,%3}, {%4,%5,%6,%7}, {%8,%9}, {%0,%1,%2,%3};"
        : "+f"(c[0]), "+f"(c[1]), "+f"(c[2]), "+f"(c[3])
        : "r"(a0), "r"(a1), "r"(a2), "r"(a3), "r"(b0), "r"(b1));
}

// ---- split grid barrier: arrive (release) / wait (acquire, absolute target) ----
__device__ __forceinline__ void bar_arrive(int tid) {
    __syncthreads();
    if (tid == 0) {
        unsigned arr;
        asm volatile("atom.release.gpu.global.add.u32 %0, [%1], %2;"
                     : "=r"(arr) : "l"(&g_count), "r"(1u));
        if (arr == NBLK - 1) {
            *(volatile unsigned*)&g_count = 0;
            asm volatile("red.release.gpu.global.add.u32 [%0], %1;" :: "l"(&g_gen), "r"(1u));
        }
    }
}
__device__ __forceinline__ void bar_wait(int tid, unsigned target) {
    if (tid == 0) {
        unsigned cur;
        do {
            asm volatile("ld.acquire.gpu.global.u32 %0, [%1];" : "=r"(cur) : "l"(&g_gen));
        } while ((int)(cur - target) < 0);
    }
    __syncthreads();
}

// ---------------- packing / init ----------------
// Wp[((bc*S + s)*32 + col)*128 + kk]; col = gate*8 + nl; H-part first
// (s<8 -> Whh k=s*128+kk; s>=8 -> Wih); row = gate*1024 + bc*8 + nl.
__global__ void pack_all(const float* __restrict__ Wih0, const float* __restrict__ Whh0,
                         const float* __restrict__ Wih1, const float* __restrict__ Whh1,
                         const float* __restrict__ Wih2, const float* __restrict__ Whh2) {
    int idx = blockIdx.x * blockDim.x + threadIdx.x;
    const float *Wih, *Whh;
    __half* Wp;
    int S, Kin, i = idx;
    if (i < L0SZ)               { Wp = g_Wp0; S = S0;  Kin = 128;  Wih = Wih0; Whh = Whh0; }
    else if (i < L0SZ + L12SZ)  { i -= L0SZ;  Wp = g_Wp1; S = S12; Kin = 1024; Wih = Wih1; Whh = Whh1; }
    else if (i < L0SZ + 2*L12SZ){ i -= L0SZ + L12SZ; Wp = g_Wp2; S = S12; Kin = 1024; Wih = Wih2; Whh = Whh2; }
    else return;
    int kk   = i & 127;
    int col  = (i >> 7) & 31;
    int rest = i >> 12;
    int s    = rest % S;
    int bc   = rest / S;
    int row  = ((col >> 3) << 10) + bc * 8 + (col & 7);
    float v  = (s < 8) ? Whh[row * 1024 + s * 128 + kk]
                       : Wih[row * Kin + (s - 8) * 128 + kk];
    Wp[i] = __float2half(v);
}

__global__ void pack_fc(const float* __restrict__ Wfc) {
    int i = blockIdx.x * blockDim.x + threadIdx.x;
    if (i < 128 * 1024) g_Wfch[i] = __float2half(Wfc[i]);
}

__global__ void init_state(const float* __restrict__ x, const float* __restrict__ h0,
                           const float* __restrict__ c0,
                           const float* __restrict__ bih0, const float* __restrict__ bhh0,
                           const float* __restrict__ bih1, const float* __restrict__ bhh1,
                           const float* __restrict__ bih2, const float* __restrict__ bhh2,
                           float* __restrict__ out) {
    int i = blockIdx.x * blockDim.x + threadIdx.x;
    if (i == 0) { g_gen = 0; g_count = 0; }     // reset barrier state each launch
    if (i < 8192) { float v = x[i]; g_In0[i] = __float2half(v); out[i] = v; }
    if (i < 3 * 65536) {
        g_Hst[i >> 16][0][i & 65535] = __float2half(h0[i]);
        g_Cst[i] = c0[i];
    }
    if (i < 4096) {
        g_bsum[i]        = bih0[i] + bhh0[i];
        g_bsum[4096 + i] = bih1[i] + bhh1[i];
        g_bsum[8192 + i] = bih2[i] + bhh2[i];
    }
}

// ---------------- main persistent kernel ----------------
extern __shared__ __half sm_raw[];

struct Ctx {
    int tid, bc;
    int ar0, au0, ar1, bcol, bu;       // cp.async indices
    unsigned AsBase, BsBase;
    unsigned aOff, bOff;               // per-lane ldmatrix offsets (bytes)
    int mh, ks;                        // warp mapping: m-half (32 rows), k-split (16 halves)
};

__device__ __forceinline__ void load_stage(const Ctx& cx,
    const __half* __restrict__ Hp, const __half* __restrict__ Xin, int ldX,
    const __half* __restrict__ wseg, int s, int slot)
{
    unsigned adst = cx.AsBase + (unsigned)(slot * ASTAGE) * 2u;
    unsigned bdst = cx.BsBase + (unsigned)(slot * BSTAGE) * 2u;
    const __half* a; int ld;
    if (s < 8) { a = Hp + s * BK; ld = 1024; }
    else       { a = Xin + (s - 8) * BK; ld = ldX; }
    cp16(adst + (unsigned)(cx.ar0 * SA + cx.au0 * 8) * 2u, a + cx.ar0 * ld + cx.au0 * 8);
    cp16(adst + (unsigned)(cx.ar1 * SA + cx.au0 * 8) * 2u, a + cx.ar1 * ld + cx.au0 * 8);
    cp16(bdst + (unsigned)(cx.bcol * SA + cx.bu * 8) * 2u,
         wseg + (size_t)s * 4096 + cx.bcol * 128 + cx.bu * 8);
}

__device__ __forceinline__ void gemm_epi(const Ctx& cx, int stages,
    const __half* __restrict__ Hp, const __half* __restrict__ Xin, int ldX,
    const __half* __restrict__ wseg, unsigned wtarget,
    const float* __restrict__ bsumL, float* __restrict__ Cl,
    __half* __restrict__ Hnext, __half* __restrict__ Xnext)
{
    float* gates = (float*)(sm_raw + GATES_OFF);    // 8 bufs of 64x33 floats

    float acc[2][2][2][4];
#pragma unroll
    for (int a = 0; a < 2; ++a)
#pragma unroll
        for (int b = 0; b < 2; ++b)
#pragma unroll
            for (int c = 0; c < 2; ++c)
#pragma unroll
                for (int d = 0; d < 4; ++d) acc[a][b][c][d] = 0.f;

    // prologue: first LA stages are H-part (barrier-independent)
#pragma unroll
    for (int s = 0; s < LA; ++s) {
        load_stage(cx, Hp, Xin, ldX, wseg, s, s);
        cp_commit();
    }

#pragma unroll 1
    for (int s = 0; s < stages; ++s) {
        asm volatile("cp.async.wait_group %0;" :: "n"(LA - 1));
        __syncthreads();
        int u = s + LA;
        if (u < stages) {
            if (u == 8) bar_wait(cx.tid, wtarget);   // publish point for X inputs
            load_stage(cx, Hp, Xin, ldX, wseg, u, u & (RING - 1));
        }
        cp_commit();

        int slot = s & (RING - 1);
        unsigned aBase = cx.AsBase + (unsigned)(slot * ASTAGE) * 2u + cx.aOff;
        unsigned bBase = cx.BsBase + (unsigned)(slot * BSTAGE) * 2u + cx.bOff;
        unsigned b0[4], b1[4];
        ldsm4(b0[0], b0[1], b0[2], b0[3], bBase);
        ldsm4(b1[0], b1[1], b1[2], b1[3], bBase + 16u * SA * 2u);
#pragma unroll
        for (int mt = 0; mt < 2; ++mt) {
            unsigned a0, a1, a2, a3;
            ldsm4(a0, a1, a2, a3, aBase + mt * (16u * SA * 2u));
            mma16816(acc[mt][0][0], a0, a1, a2, a3, b0[0], b0[1]);
            mma16816(acc[mt][0][1], a0, a1, a2, a3, b0[2], b0[3]);
            mma16816(acc[mt][1][0], a0, a1, a2, a3, b1[0], b1[1]);
            mma16816(acc[mt][1][1], a0, a1, a2, a3, b1[2], b1[3]);
        }
    }

    // store partial gates (per k-split buffer)
    {
        const int lane = cx.tid & 31;
        float* gk = gates + cx.ks * (64 * 33);
        int r = lane >> 2, p2 = (lane & 3) * 2;
#pragma unroll
        for (int mt = 0; mt < 2; ++mt)
#pragma unroll
            for (int hb = 0; hb < 2; ++hb)
#pragma unroll
                for (int n8 = 0; n8 < 2; ++n8) {
                    int row = cx.mh * 32 + mt * 16 + r;
                    int col = hb * 16 + n8 * 8 + p2;
                    float* q = acc[mt][hb][n8];
                    gk[row * 33 + col]           = q[0];
                    gk[row * 33 + col + 1]       = q[1];
                    gk[(row + 8) * 33 + col]     = q[2];
                    gk[(row + 8) * 33 + col + 1] = q[3];
                }
    }
    __syncthreads();

    // fused LSTM cell epilogue: 512 threads, one (batch, hid) each
    {
        int b = cx.tid >> 3, nl = cx.tid & 7;
        int ng = cx.bc * 8 + nl;
        int e = b * 33 + nl;
        float gi = 0.f, gf = 0.f, gg = 0.f, go = 0.f;
#pragma unroll
        for (int k = 0; k < NKS; ++k) {
            const float* g = gates + k * (64 * 33);
            gi += g[e];
            gf += g[e + 8];
            gg += g[e + 16];
            go += g[e + 24];
        }
        gi += bsumL[ng]; gf += bsumL[1024 + ng];
        gg += bsumL[2048 + ng]; go += bsumL[3072 + ng];
        float c  = Cl[b * 1024 + ng];
        float cn = sigf(gf) * c + sigf(gi) * tanhf(gg);
        float h  = sigf(go) * tanhf(cn);
        Cl[b * 1024 + ng] = cn;
        __half hh = __float2half(h);
        Hnext[b * 1024 + ng] = hh;
        Xnext[b * 1024 + ng] = hh;
    }
    // bar_arrive() in caller provides the trailing __syncthreads
}

__global__ void __launch_bounds__(NTHR, 1)
lstm_main(const float* __restrict__ x, const float* __restrict__ bfc,
          float* __restrict__ out)
{
    const int tid = threadIdx.x, bc = blockIdx.x;
    Ctx cx;
    cx.tid = tid; cx.bc = bc;
    cx.ar0 = tid >> 4;          cx.au0 = tid & 15;
    cx.ar1 = (tid + 512) >> 4;
    cx.bcol = tid >> 4;         cx.bu = tid & 15;
    cx.AsBase = smaddr(sm_raw);
    cx.BsBase = smaddr(sm_raw + RING * ASTAGE);
    {
        const int lane = tid & 31, wid = tid >> 5;
        cx.mh = wid & 1;                       // m-half (32 rows)
        cx.ks = wid >> 1;                      // k-chunk 0..7 (16 halves each)
        int aRow = cx.mh * 32 + ((lane >> 3) & 1) * 8 + (lane & 7);
        cx.aOff = (unsigned)(aRow * SA + (lane >> 4) * 8 + cx.ks * 16) * 2u;
        int bRow = ((lane >> 4) & 1) * 8 + (lane & 7);
        cx.bOff = (unsigned)(bRow * SA + ((lane >> 3) & 1) * 8 + cx.ks * 16) * 2u;
    }
    __half* sWfc = sm_raw + WFC_OFF;

    // cache this CTA's fc weight slice in smem (8 rows x 1024 halves)
    {
        const int cg = bc & 15;
        const __half* src = g_Wfch + cg * 8 * 1024;
#pragma unroll
        for (int i = 0; i < 2; ++i) {
            int e = (tid + i * 512) * 8;
            cp16(smaddr(sWfc + e), src + e);
        }
        cp_commit();
        asm volatile("cp.async.wait_group 0;");
        __syncthreads();
    }

    const __half* Wb0 = g_Wp0 + (size_t)bc * S0 * 4096;
    const __half* Wb1 = g_Wp1 + (size_t)bc * S12 * 4096;
    const __half* Wb2 = g_Wp2 + (size_t)bc * S12 * 4096;

#pragma unroll 1
    for (int t = 0; t < T_STEPS - 1; ++t) {
        int p = t & 1;
        unsigned b4 = (unsigned)(t * 4);

        // L0: H-stages overlap In0 barrier (target b4); X-stage at u==8
        gemm_epi(cx, S0, g_Hst[0][p], g_In0, 128, Wb0, b4,
                 g_bsum, g_Cst, g_Hst[0][p ^ 1], g_X1);
        bar_arrive(tid);                                     // -> gen b4+1 (X1, h0)

        gemm_epi(cx, S12, g_Hst[1][p], g_X1, 1024, Wb1, b4 + 1,
                 g_bsum + 4096, g_Cst + 65536, g_Hst[1][p ^ 1], g_X2);
        bar_arrive(tid);                                     // -> gen b4+2 (X2, h1)

        gemm_epi(cx, S12, g_Hst[2][p], g_X2, 1024, Wb2, b4 + 2,
                 g_bsum + 8192, g_Cst + 131072, g_Hst[2][p ^ 1], g_Xfc);
        bar_arrive(tid);                                     // -> gen b4+3 (Xfc, h2)
        bar_wait(tid, b4 + 3);                               // exposed: fc needs all Xfc

        // fc: out = sigmoid(h2 @ Wfc^T + bfc); blocks tile 8(batch) x 16(cols)
        {
            int br = bc >> 4, cg = bc & 15;
            int o = tid >> 3, part = tid & 7;
            int b = br * 8 + (o >> 3);
            int dl = o & 7;
            int d = cg * 8 + dl;
            const float4* hp = (const float4*)(g_Xfc + b * 1024) + part * 16;
            const float4* wp = (const float4*)(sWfc + dl * 1024) + part * 16;
            float acc = 0.f;
#pragma unroll
            for (int k = 0; k < 16; ++k) {
                float4 hv = __ldcg(hp + k);
                float4 wv = wp[k];
                const __half2* h2 = (const __half2*)&hv;
                const __half2* w2 = (const __half2*)&wv;
#pragma unroll
                for (int j = 0; j < 4; ++j) {
                    float2 hf = __half22float2(h2[j]);
                    float2 wf = __half22float2(w2[j]);
                    acc = fmaf(hf.x, wf.x, acc);
                    acc = fmaf(hf.y, wf.y, acc);
                }
            }
            acc += __shfl_xor_sync(0xffffffff, acc, 1);
            acc += __shfl_xor_sync(0xffffffff, acc, 2);
            acc += __shfl_xor_sync(0xffffffff, acc, 4);
            if (part == 0) {
                float z = sigf(acc + bfc[d]);
                float v = (t + 1 < PLEN) ? x[(size_t)(t + 1) * 8192 + b * 128 + d] : z;
                out[(size_t)(t + 1) * 8192 + b * 128 + d] = v;
                g_In0[b * 128 + d] = __float2half(v);
            }
        }
        bar_arrive(tid);                                     // -> gen b4+4 (In0 for t+1)
        // next step's L0 overlaps this barrier with its 8 H-stages
    }
}

// ---------------- launch (lstm_main is launch #4 for ncu) ----------------
extern "C" void kernel_launch(void* const* d_in, const int* in_sizes, int n_in,
                              void* d_out, int out_size) {
    const float* x    = (const float*)d_in[0];
    const float* h0   = (const float*)d_in[1];
    const float* c0   = (const float*)d_in[2];
    const float* Wih0 = (const float*)d_in[3];
    const float* Whh0 = (const float*)d_in[4];
    const float* bih0 = (const float*)d_in[5];
    const float* bhh0 = (const float*)d_in[6];
    const float* Wih1 = (const float*)d_in[7];
    const float* Whh1 = (const float*)d_in[8];
    const float* bih1 = (const float*)d_in[9];
    const float* bhh1 = (const float*)d_in[10];
    const float* Wih2 = (const float*)d_in[11];
    const float* Whh2 = (const float*)d_in[12];
    const float* bih2 = (const float*)d_in[13];
    const float* bhh2 = (const float*)d_in[14];
    const float* Wfc  = (const float*)d_in[15];
    const float* bfc  = (const float*)d_in[16];
    float* out = (float*)d_out;

    static bool attr_done = false;
    if (!attr_done) {
        cudaFuncSetAttribute(lstm_main, cudaFuncAttributeMaxDynamicSharedMemorySize,
                             SMEM_BYTES);
        attr_done = true;
    }

    int total = L0SZ + 2 * L12SZ;
    pack_all<<<(total + 255) / 256, 256>>>(Wih0, Whh0, Wih1, Whh1, Wih2, Whh2);
    pack_fc<<<512, 256>>>(Wfc);
    init_state<<<768, 256>>>(x, h0, c0, bih0, bhh0, bih1, bhh1, bih2, bhh2, out);
    lstm_main<<<NBLK, NTHR, SMEM_BYTES>>>(x, bfc, out);
}